// round 9
// baseline (speedup 1.0000x reference)
#include <cuda_runtime.h>
#include <cuda_bf16.h>
#include <math.h>
#include <stdint.h>

// ---------------------------------------------------------------------------
// Problem constants
// ---------------------------------------------------------------------------
#define BATCH 8
#define HGT   128
#define WID   128
#define CH    192
#define NHEAD 6
#define HD    32
#define WS    8
#define SS    4
#define NTOK  64
#define NWIN  (BATCH * 16 * 16)       // 2048
#define TOT   (BATCH * HGT * WID)     // 131072
#define HID   (CH * 4)                // 768
#define QSCALE 0.17677669529663687f   // 32^-0.5

typedef __nv_bfloat16 bf16;

// ---------------------------------------------------------------------------
// Scratch (static device globals; allocation-free)
// ---------------------------------------------------------------------------
__device__ __align__(256) bf16  g_xw  [(size_t)TOT * CH];
__device__ __align__(256) bf16  g_qkvb[(size_t)TOT * 3 * CH];
__device__ __align__(256) bf16  g_attn[(size_t)TOT * CH];
__device__ __align__(256) float g_x1  [(size_t)TOT * CH];
__device__ __align__(256) bf16  g_ln2 [(size_t)TOT * CH];
__device__ __align__(256) bf16  g_h1  [(size_t)TOT * HID];
// one combined transposed-weight arena: [qkv | proj | fc1 | fc2]
#define W_QKV_OFF  0
#define W_PROJ_OFF (3 * CH * CH)
#define W_FC1_OFF  (W_PROJ_OFF + CH * CH)
#define W_FC2_OFF  (W_FC1_OFF + HID * CH)
#define W_TOTAL    (W_FC2_OFF + CH * HID)
__device__ __align__(256) bf16  g_wall[W_TOTAL];

// ---------------------------------------------------------------------------
// helpers
// ---------------------------------------------------------------------------
__device__ __forceinline__ uint32_t smem_u32(const void* p) {
    uint32_t a;
    asm("{ .reg .u64 t; cvta.to.shared.u64 t, %1; cvt.u32.u64 %0, t; }" : "=r"(a) : "l"(p));
    return a;
}
__device__ __forceinline__ void cpasync16(uint32_t so, const void* g) {
    asm volatile("cp.async.cg.shared.global [%0], [%1], 16;"
                 :: "r"(so), "l"(__cvta_generic_to_global(g)) : "memory");
}
__device__ __forceinline__ void ldm_x4(uint32_t* r, uint32_t addr) {
    asm volatile("ldmatrix.sync.aligned.m8n8.x4.shared.b16 {%0,%1,%2,%3}, [%4];"
                 : "=r"(r[0]), "=r"(r[1]), "=r"(r[2]), "=r"(r[3]) : "r"(addr));
}
__device__ __forceinline__ void ldm_x4t(uint32_t* r, uint32_t addr) {
    asm volatile("ldmatrix.sync.aligned.m8n8.x4.trans.shared.b16 {%0,%1,%2,%3}, [%4];"
                 : "=r"(r[0]), "=r"(r[1]), "=r"(r[2]), "=r"(r[3]) : "r"(addr));
}
__device__ __forceinline__ void mma16816(float* d, const uint32_t* a, const uint32_t* b) {
    asm volatile("mma.sync.aligned.m16n8k16.row.col.f32.bf16.bf16.f32 "
                 "{%0,%1,%2,%3}, {%4,%5,%6,%7}, {%8,%9}, {%0,%1,%2,%3};"
                 : "+f"(d[0]), "+f"(d[1]), "+f"(d[2]), "+f"(d[3])
                 : "r"(a[0]), "r"(a[1]), "r"(a[2]), "r"(a[3]), "r"(b[0]), "r"(b[1]));
}
__device__ __forceinline__ uint32_t packbf(float a, float b) {
    __nv_bfloat162 t = __floats2bfloat162_rn(a, b);
    return *(uint32_t*)&t;
}

// ---------------------------------------------------------------------------
// Combined weight transpose+convert (one launch).  Wt[n*K+k] = bf16(W[k*N+n])
// ---------------------------------------------------------------------------
__global__ void wconv_all(const float* __restrict__ Wqkv, const float* __restrict__ Wproj,
                          const float* __restrict__ Wfc1, const float* __restrict__ Wfc2,
                          bf16* __restrict__ arena) {
    int i = blockIdx.x * 256 + threadIdx.x;
    const float* W; int K, N, off;
    if (i < W_PROJ_OFF)            { W = Wqkv;  K = CH;  N = 3 * CH; off = 0;          }
    else if (i < W_FC1_OFF)        { W = Wproj; K = CH;  N = CH;     off = W_PROJ_OFF; }
    else if (i < W_FC2_OFF)        { W = Wfc1;  K = CH;  N = HID;    off = W_FC1_OFF;  }
    else if (i < W_TOTAL)          { W = Wfc2;  K = HID; N = CH;     off = W_FC2_OFF;  }
    else return;
    int j = i - off;
    int n = j / K, k = j - n * K;
    arena[i] = __float2bfloat16(W[(size_t)k * N + n]);
}

// ---------------------------------------------------------------------------
// K1: LN1 + roll(-4,-4) + window partition -> bf16.  Warp per row.
// ---------------------------------------------------------------------------
__global__ void __launch_bounds__(256) ln1_kernel(const float* __restrict__ x,
                                                  const float* __restrict__ g,
                                                  const float* __restrict__ b,
                                                  bf16* __restrict__ out) {
    int row  = blockIdx.x * 8 + (threadIdx.x >> 5);
    int lane = threadIdx.x & 31;
    int win = row >> 6, n = row & 63;
    int bimg = win >> 8;
    int wii  = win & 255;
    int sy = ((wii >> 4) * 8 + (n >> 3) + SS) & 127;
    int sx = ((wii & 15) * 8 + (n & 7) + SS) & 127;
    const float* xr = x + ((size_t)bimg * (HGT * WID) + sy * WID + sx) * CH;

    float v[6];
    #pragma unroll
    for (int i = 0; i < 6; i++) v[i] = xr[lane + 32 * i];
    float s = v[0] + v[1] + v[2] + v[3] + v[4] + v[5];
    #pragma unroll
    for (int o = 16; o > 0; o >>= 1) s += __shfl_xor_sync(~0u, s, o);
    float mu = s * (1.0f / CH);
    float q = 0.f;
    #pragma unroll
    for (int i = 0; i < 6; i++) { v[i] -= mu; q += v[i] * v[i]; }
    #pragma unroll
    for (int o = 16; o > 0; o >>= 1) q += __shfl_xor_sync(~0u, q, o);
    float rs = rsqrtf(q * (1.0f / CH) + 1e-5f);
    bf16* orow = out + (size_t)row * CH;
    #pragma unroll
    for (int i = 0; i < 6; i++) {
        int c = lane + 32 * i;
        orow[c] = __float2bfloat16(v[i] * rs * g[c] + b[c]);
    }
}

// ---------------------------------------------------------------------------
// LN2 only (token order).  Warp per row.
// ---------------------------------------------------------------------------
__global__ void __launch_bounds__(256) ln2_kernel(const float* __restrict__ x1,
                                                  const float* __restrict__ g,
                                                  const float* __restrict__ b,
                                                  bf16* __restrict__ out) {
    int row  = blockIdx.x * 8 + (threadIdx.x >> 5);
    int lane = threadIdx.x & 31;
    const float* xr = x1 + (size_t)row * CH;
    float v[6];
    #pragma unroll
    for (int i = 0; i < 6; i++) v[i] = xr[lane + 32 * i];
    float s = v[0] + v[1] + v[2] + v[3] + v[4] + v[5];
    #pragma unroll
    for (int o = 16; o > 0; o >>= 1) s += __shfl_xor_sync(~0u, s, o);
    float mu = s * (1.0f / CH);
    float q = 0.f;
    #pragma unroll
    for (int i = 0; i < 6; i++) { v[i] -= mu; q += v[i] * v[i]; }
    #pragma unroll
    for (int o = 16; o > 0; o >>= 1) q += __shfl_xor_sync(~0u, q, o);
    float rs = rsqrtf(q * (1.0f / CH) + 1e-5f);
    bf16* orow = out + (size_t)row * CH;
    #pragma unroll
    for (int i = 0; i < 6; i++) {
        int c = lane + 32 * i;
        orow[c] = __float2bfloat16(v[i] * rs * g[c] + b[c]);
    }
}

// window-layout row -> token index (reverse partition + roll(+4,+4))
__device__ __forceinline__ int row2tok(int row) {
    int win = row >> 6, n = row & 63;
    int bimg = win >> 8;
    int wii  = win & 255;
    int y = ((wii >> 4) * 8 + (n >> 3) + SS) & 127;
    int x = ((wii & 15) * 8 + (n & 7) + SS) & 127;
    return bimg * (HGT * WID) + y * WID + x;
}

#define PITCH 144                    // 64 bf16 = 128B data + 16B pad

// ---------------------------------------------------------------------------
// A-resident GEMM for K=192: one CTA per 128 rows; A tile (128x192) resident
// in smem (3 chunks of K=64); loops over NT tiles of BN=96, streaming B
// through a 4-slot cp.async ring.  2 CTAs/SM.
// EPI 1: gelu->bf16   3: qkv bf16 (scale q cols)   4: proj permute+res->x1
// ---------------------------------------------------------------------------
#define AR_CH  (128 * PITCH)                 // 18432 per A chunk
#define AR_B   (96 * PITCH)                  // 13824 per B slot
#define AR_BOFF (3 * AR_CH)                  // 55296
#define ARSMEM (AR_BOFF + 4 * AR_B)          // 110592

__device__ __forceinline__ void ar_loadA(uint32_t sb, const bf16* Ag, int c, int tid) {
    #pragma unroll
    for (int i = 0; i < 4; i++) {            // 128 rows x 8 segs = 1024
        int t = tid + i * 256;
        int row = t >> 3, seg = t & 7;
        cpasync16(sb + c * AR_CH + row * PITCH + seg * 16,
                  Ag + (size_t)row * CH + c * 64 + seg * 8);
    }
}
__device__ __forceinline__ void ar_loadB(uint32_t sb, const bf16* Bt, int step, int tid) {
    int tile = step / 3, chunk = step - tile * 3, slot = step & 3;
    #pragma unroll
    for (int i = 0; i < 3; i++) {            // 96 rows x 8 segs = 768
        int t = tid + i * 256;
        int row = t >> 3, seg = t & 7;
        cpasync16(sb + AR_BOFF + slot * AR_B + row * PITCH + seg * 16,
                  Bt + ((size_t)tile * 96 + row) * CH + chunk * 64 + seg * 8);
    }
}

template <int EPI, int NT>
__global__ void __launch_bounds__(256) agemm(const bf16* __restrict__ A,
                                             const bf16* __restrict__ Bt,
                                             const float* __restrict__ bias,
                                             const float* __restrict__ res,
                                             void* __restrict__ Cout) {
    extern __shared__ __align__(128) char smem[];
    __shared__ float sbias[NT * 96];

    const int Nbig = NT * 96;
    const int S = NT * 3;
    const int tid  = threadIdx.x;
    const int lane = tid & 31;
    const int w    = tid >> 5;
    const int bm   = blockIdx.x * 128;
    const int wm   = (w & 3) * 32;
    const int wn   = (w >> 2) * 48;

    const uint32_t sb = smem_u32(smem);
    for (int i = tid; i < Nbig; i += 256) sbias[i] = bias[i];

    const bf16* Ag = A + (size_t)bm * CH;

    const int aRow = (lane & 7) + ((lane >> 3) & 1) * 8;
    const int aCol = (lane >> 4) * 8;
    const int bRow = (lane & 7) + (lane >> 4) * 8;
    const int bCol = ((lane >> 3) & 1) * 8;
    const int g = lane >> 2, t4 = lane & 3;

    int tok0 = 0, tok1 = 0;
    if (EPI == 4) {
        int row0 = bm + wm + g;
        tok0 = row2tok(row0);
        tok1 = row2tok(row0 + 8);   // rows row0+16.. computed via offset below
    }

    // prologue: 3 groups, each = one A chunk + one B step
    #pragma unroll
    for (int c = 0; c < 3; c++) {
        ar_loadA(sb, Ag, c, tid);
        ar_loadB(sb, Bt, c, tid);
        asm volatile("cp.async.commit_group;" ::: "memory");
    }

    int s = 0;
    #pragma unroll 1
    for (int nt = 0; nt < NT; nt++) {
        float acc[2][6][4];
        #pragma unroll
        for (int i = 0; i < 2; i++)
            #pragma unroll
            for (int j = 0; j < 6; j++)
                #pragma unroll
                for (int k = 0; k < 4; k++) acc[i][j][k] = 0.0f;

        #pragma unroll 1
        for (int cc = 0; cc < 3; cc++, s++) {
            int lead = S - 1 - s;
            if (lead >= 2)      asm volatile("cp.async.wait_group 2;" ::: "memory");
            else if (lead == 1) asm volatile("cp.async.wait_group 1;" ::: "memory");
            else                asm volatile("cp.async.wait_group 0;" ::: "memory");
            __syncthreads();

            const uint32_t cA = sb + cc * AR_CH;
            const uint32_t cB = sb + AR_BOFF + (s & 3) * AR_B;

            #pragma unroll
            for (int ks = 0; ks < 4; ks++) {
                uint32_t af[2][4], bf_[3][4];
                #pragma unroll
                for (int mt = 0; mt < 2; mt++)
                    ldm_x4(af[mt], cA + (wm + mt * 16 + aRow) * PITCH + (ks * 16 + aCol) * 2);
                #pragma unroll
                for (int nt2 = 0; nt2 < 3; nt2++)
                    ldm_x4(bf_[nt2], cB + (wn + nt2 * 16 + bRow) * PITCH + (ks * 16 + bCol) * 2);
                #pragma unroll
                for (int mt = 0; mt < 2; mt++)
                    #pragma unroll
                    for (int nt2 = 0; nt2 < 3; nt2++) {
                        mma16816(acc[mt][2 * nt2 + 0], af[mt], bf_[nt2] + 0);
                        mma16816(acc[mt][2 * nt2 + 1], af[mt], bf_[nt2] + 2);
                    }
            }

            if (s + 3 < S) {
                ar_loadB(sb, Bt, s + 3, tid);
                asm volatile("cp.async.commit_group;" ::: "memory");
            }
        }

        // epilogue for tile nt
        #pragma unroll
        for (int mi = 0; mi < 2; mi++) {
            #pragma unroll
            for (int ni = 0; ni < 6; ni++) {
                int colL = wn + ni * 8 + t4 * 2;
                int col  = nt * 96 + colL;
                int row0 = bm + wm + mi * 16 + g;
                int row1 = row0 + 8;
                float v00 = acc[mi][ni][0] + sbias[col];
                float v01 = acc[mi][ni][1] + sbias[col + 1];
                float v10 = acc[mi][ni][2] + sbias[col];
                float v11 = acc[mi][ni][3] + sbias[col + 1];
                if (EPI == 1) {
                    v00 = v00 * normcdff(v00); v01 = v01 * normcdff(v01);
                    v10 = v10 * normcdff(v10); v11 = v11 * normcdff(v11);
                    bf16* C = (bf16*)Cout;
                    *(__nv_bfloat162*)(C + (size_t)row0 * Nbig + col) = __floats2bfloat162_rn(v00, v01);
                    *(__nv_bfloat162*)(C + (size_t)row1 * Nbig + col) = __floats2bfloat162_rn(v10, v11);
                } else if (EPI == 3) {
                    float sc = (col < CH) ? QSCALE : 1.0f;
                    bf16* C = (bf16*)Cout;
                    *(__nv_bfloat162*)(C + (size_t)row0 * Nbig + col) = __floats2bfloat162_rn(v00 * sc, v01 * sc);
                    *(__nv_bfloat162*)(C + (size_t)row1 * Nbig + col) = __floats2bfloat162_rn(v10 * sc, v11 * sc);
                } else { // EPI 4
                    int t0 = (mi == 0) ? tok0 : row2tok(row0);
                    int t1 = (mi == 0) ? tok1 : row2tok(row1);
                    float2 r0 = *(const float2*)(res + (size_t)t0 * Nbig + col);
                    float2 r1 = *(const float2*)(res + (size_t)t1 * Nbig + col);
                    float* C = (float*)Cout;
                    *(float2*)(C + (size_t)t0 * Nbig + col) = make_float2(v00 + r0.x, v01 + r0.y);
                    *(float2*)(C + (size_t)t1 * Nbig + col) = make_float2(v10 + r1.x, v11 + r1.y);
                }
            }
        }
    }
}

// ---------------------------------------------------------------------------
// Streaming GEMM for fc2 (K=768): BM=128 BN=96 BK=64, 3-stage ring.
// EPI 2: +bias +res -> fp32
// ---------------------------------------------------------------------------
#define A_STG (128 * PITCH)
#define B_STG (96 * PITCH)
#define STG   (A_STG + B_STG)
#define GSMEM (3 * STG)

__device__ __forceinline__ void load_stage(uint32_t st, const bf16* Ag, const bf16* Bg,
                                           int Kbig, int tid) {
    #pragma unroll
    for (int i = 0; i < 4; i++) {
        int t = tid + i * 256;
        int row = t >> 3, seg = t & 7;
        cpasync16(st + row * PITCH + seg * 16, Ag + (size_t)row * Kbig + seg * 8);
    }
    #pragma unroll
    for (int i = 0; i < 3; i++) {
        int t = tid + i * 256;
        int row = t >> 3, seg = t & 7;
        cpasync16(st + A_STG + row * PITCH + seg * 16, Bg + (size_t)row * Kbig + seg * 8);
    }
}

__global__ void __launch_bounds__(256) hgemm_fc2(const bf16* __restrict__ A,
                                                 const bf16* __restrict__ Bt,
                                                 const float* __restrict__ bias,
                                                 const float* __restrict__ res,
                                                 float* __restrict__ Cout) {
    extern __shared__ __align__(128) char smem[];
    __shared__ float sbias[96];

    const int Kbig = HID, Nbig = CH;
    const int tid  = threadIdx.x;
    const int lane = tid & 31;
    const int w    = tid >> 5;
    const int bm   = blockIdx.y * 128;
    const int bn   = blockIdx.x * 96;
    const int wm   = (w & 3) * 32;
    const int wn   = (w >> 2) * 48;

    const uint32_t sb = smem_u32(smem);
    if (tid < 96) sbias[tid] = bias[bn + tid];

    const bf16* Ag = A  + (size_t)bm * Kbig;
    const bf16* Bg = Bt + (size_t)bn * Kbig;
    const int NC = Kbig >> 6;

    const int aRow = (lane & 7) + ((lane >> 3) & 1) * 8;
    const int aCol = (lane >> 4) * 8;
    const int bRow = (lane & 7) + (lane >> 4) * 8;
    const int bCol = ((lane >> 3) & 1) * 8;

    float acc[2][6][4];
    #pragma unroll
    for (int i = 0; i < 2; i++)
        #pragma unroll
        for (int j = 0; j < 6; j++)
            #pragma unroll
            for (int k = 0; k < 4; k++) acc[i][j][k] = 0.0f;

    load_stage(sb, Ag, Bg, Kbig, tid);
    asm volatile("cp.async.commit_group;" ::: "memory");
    load_stage(sb + STG, Ag + 64, Bg + 64, Kbig, tid);
    asm volatile("cp.async.commit_group;" ::: "memory");

    for (int c = 0; c < NC; c++) {
        if (c + 1 < NC) asm volatile("cp.async.wait_group 1;" ::: "memory");
        else            asm volatile("cp.async.wait_group 0;" ::: "memory");
        __syncthreads();

        if (c + 2 < NC) {
            load_stage(sb + ((c + 2) % 3) * STG,
                       Ag + (size_t)(c + 2) * 64, Bg + (size_t)(c + 2) * 64, Kbig, tid);
            asm volatile("cp.async.commit_group;" ::: "memory");
        }

        const uint32_t cA = sb + (c % 3) * STG;
        const uint32_t cB = cA + A_STG;

        #pragma unroll
        for (int ks = 0; ks < 4; ks++) {
            uint32_t af[2][4], bf_[3][4];
            #pragma unroll
            for (int mt = 0; mt < 2; mt++)
                ldm_x4(af[mt], cA + (wm + mt * 16 + aRow) * PITCH + (ks * 16 + aCol) * 2);
            #pragma unroll
            for (int nt = 0; nt < 3; nt++)
                ldm_x4(bf_[nt], cB + (wn + nt * 16 + bRow) * PITCH + (ks * 16 + bCol) * 2);
            #pragma unroll
            for (int mt = 0; mt < 2; mt++)
                #pragma unroll
                for (int nt = 0; nt < 3; nt++) {
                    mma16816(acc[mt][2 * nt + 0], af[mt], bf_[nt] + 0);
                    mma16816(acc[mt][2 * nt + 1], af[mt], bf_[nt] + 2);
                }
        }
    }

    const int g = lane >> 2, t4 = lane & 3;
    #pragma unroll
    for (int mi = 0; mi < 2; mi++) {
        #pragma unroll
        for (int ni = 0; ni < 6; ni++) {
            int colL = wn + ni * 8 + t4 * 2;
            int col  = bn + colL;
            int row0 = bm + wm + mi * 16 + g;
            int row1 = row0 + 8;
            float2 r0 = *(const float2*)(res + (size_t)row0 * Nbig + col);
            float2 r1 = *(const float2*)(res + (size_t)row1 * Nbig + col);
            *(float2*)(Cout + (size_t)row0 * Nbig + col) =
                make_float2(acc[mi][ni][0] + sbias[colL] + r0.x,
                            acc[mi][ni][1] + sbias[colL + 1] + r0.y);
            *(float2*)(Cout + (size_t)row1 * Nbig + col) =
                make_float2(acc[mi][ni][2] + sbias[colL] + r1.x,
                            acc[mi][ni][3] + sbias[colL + 1] + r1.y);
        }
    }
}

// ---------------------------------------------------------------------------
// K3: attention with mma.sync.  One CTA per window, 384 thr = 2 warps/head.
// ---------------------------------------------------------------------------
#define APB 400
#define ATTN_SMEM (3 * 64 * APB + 6 * 225 * 4 + 64 * 4)

__global__ void __launch_bounds__(384) attn_mma(const bf16* __restrict__ qkv,
                                                const float* __restrict__ bt,
                                                bf16* __restrict__ out) {
    extern __shared__ __align__(128) char sm[];
    const uint32_t sb = smem_u32(sm);
    const uint32_t sQ = sb, sK = sb + 64 * APB, sV = sb + 128 * APB;
    float* sbias = (float*)(sm + 3 * 64 * APB);
    int*   sreg  = (int*)(sm + 3 * 64 * APB + 6 * 225 * 4);

    const int tid  = threadIdx.x;
    const int win  = blockIdx.x;
    const int lane = tid & 31;
    const int wid  = tid >> 5;
    const int head = wid >> 1, half = wid & 1;
    const int g = lane >> 2, t4 = lane & 3;

    const bf16* gbase = qkv + (size_t)win * NTOK * (3 * CH);
    #pragma unroll
    for (int i = 0; i < 12; i++) {
        int c = tid + i * 384;
        int r = c / 72, w2 = c % 72;
        int tile = w2 / 24, seg = w2 % 24;
        cpasync16(sb + tile * (64 * APB) + r * APB + seg * 16,
                  gbase + (size_t)r * (3 * CH) + tile * CH + seg * 8);
    }
    asm volatile("cp.async.commit_group;" ::: "memory");

    for (int i = tid; i < 6 * 225; i += 384) {
        int h = i / 225, p = i - h * 225;
        sbias[i] = bt[p * NHEAD + h];
    }
    if (tid < 64) {
        int wii = win & 255;
        int y = (wii >> 4) * 8 + (tid >> 3);
        int x = (wii & 15) * 8 + (tid & 7);
        int ry = (y < 120) ? 0 : (y < 124 ? 1 : 2);
        int rx = (x < 120) ? 0 : (x < 124 ? 1 : 2);
        sreg[tid] = ry * 3 + rx;
    }
    asm volatile("cp.async.wait_group 0;" ::: "memory");
    __syncthreads();

    const int aRow = (lane & 7) + ((lane >> 3) & 1) * 8;
    const int aCol = (lane >> 4) * 8;
    const int bRow = (lane & 7) + (lane >> 4) * 8;
    const int bCol = ((lane >> 3) & 1) * 8;

    uint32_t qf[2][2][4];
    #pragma unroll
    for (int mt = 0; mt < 2; mt++)
        #pragma unroll
        for (int ks = 0; ks < 2; ks++)
            ldm_x4(qf[mt][ks],
                   sQ + (half * 32 + mt * 16 + aRow) * APB + (head * 32 + ks * 16 + aCol) * 2);

    float sc[2][8][4];
    #pragma unroll
    for (int a = 0; a < 2; a++)
        #pragma unroll
        for (int b2 = 0; b2 < 8; b2++)
            #pragma unroll
            for (int c2 = 0; c2 < 4; c2++) sc[a][b2][c2] = 0.f;

    #pragma unroll
    for (int nt = 0; nt < 4; nt++) {
        uint32_t kb[2][4];
        #pragma unroll
        for (int ks = 0; ks < 2; ks++)
            ldm_x4(kb[ks], sK + (nt * 16 + bRow) * APB + (head * 32 + ks * 16 + bCol) * 2);
        #pragma unroll
        for (int mt = 0; mt < 2; mt++)
            #pragma unroll
            for (int ks = 0; ks < 2; ks++) {
                mma16816(sc[mt][2 * nt + 0], qf[mt][ks], kb[ks] + 0);
                mma16816(sc[mt][2 * nt + 1], qf[mt][ks], kb[ks] + 2);
            }
    }

    const float* bh = sbias + head * 225;
    float inv[2][2];
    #pragma unroll
    for (int mt = 0; mt < 2; mt++) {
        #pragma unroll
        for (int s = 0; s < 2; s++) {
            int row = half * 32 + mt * 16 + g + 8 * s;
            int ty = row >> 3, tx = row & 7;
            int myreg = sreg[row];
            float mx = -1e30f;
            #pragma unroll
            for (int nt = 0; nt < 8; nt++)
                #pragma unroll
                for (int i = 0; i < 2; i++) {
                    int col = nt * 8 + t4 * 2 + i;
                    float v = sc[mt][nt][2 * s + i]
                            + bh[(ty - (col >> 3) + 7) * 15 + (tx - (col & 7) + 7)];
                    if (sreg[col] != myreg) v -= 100.f;
                    sc[mt][nt][2 * s + i] = v;
                    mx = fmaxf(mx, v);
                }
            mx = fmaxf(mx, __shfl_xor_sync(~0u, mx, 1));
            mx = fmaxf(mx, __shfl_xor_sync(~0u, mx, 2));
            float sum = 0.f;
            #pragma unroll
            for (int nt = 0; nt < 8; nt++)
                #pragma unroll
                for (int i = 0; i < 2; i++) {
                    float e = __expf(sc[mt][nt][2 * s + i] - mx);
                    sc[mt][nt][2 * s + i] = e;
                    sum += e;
                }
            sum += __shfl_xor_sync(~0u, sum, 1);
            sum += __shfl_xor_sync(~0u, sum, 2);
            inv[mt][s] = 1.0f / sum;
        }
    }

    uint32_t pf[2][4][4];
    #pragma unroll
    for (int mt = 0; mt < 2; mt++)
        #pragma unroll
        for (int kt = 0; kt < 4; kt++) {
            pf[mt][kt][0] = packbf(sc[mt][2 * kt][0] * inv[mt][0], sc[mt][2 * kt][1] * inv[mt][0]);
            pf[mt][kt][1] = packbf(sc[mt][2 * kt][2] * inv[mt][1], sc[mt][2 * kt][3] * inv[mt][1]);
            pf[mt][kt][2] = packbf(sc[mt][2 * kt + 1][0] * inv[mt][0], sc[mt][2 * kt + 1][1] * inv[mt][0]);
            pf[mt][kt][3] = packbf(sc[mt][2 * kt + 1][2] * inv[mt][1], sc[mt][2 * kt + 1][3] * inv[mt][1]);
        }

    float o[2][4][4];
    #pragma unroll
    for (int a = 0; a < 2; a++)
        #pragma unroll
        for (int b2 = 0; b2 < 4; b2++)
            #pragma unroll
            for (int c2 = 0; c2 < 4; c2++) o[a][b2][c2] = 0.f;

    #pragma unroll
    for (int kt = 0; kt < 4; kt++)
        #pragma unroll
        for (int nv = 0; nv < 2; nv++) {
            uint32_t vb[4];
            ldm_x4t(vb, sV + (kt * 16 + (lane & 7) + ((lane >> 3) & 1) * 8) * APB
                       + (head * 32 + nv * 16 + (lane >> 4) * 8) * 2);
            #pragma unroll
            for (int mt = 0; mt < 2; mt++) {
                mma16816(o[mt][2 * nv + 0], pf[mt][kt], vb + 0);
                mma16816(o[mt][2 * nv + 1], pf[mt][kt], vb + 2);
            }
        }

    bf16* ob = out + (size_t)win * NTOK * CH + head * HD;
    #pragma unroll
    for (int mt = 0; mt < 2; mt++)
        #pragma unroll
        for (int nv = 0; nv < 4; nv++) {
            int r0 = half * 32 + mt * 16 + g;
            int co = nv * 8 + t4 * 2;
            *(__nv_bfloat162*)(ob + (size_t)r0 * CH + co) =
                __floats2bfloat162_rn(o[mt][nv][0], o[mt][nv][1]);
            *(__nv_bfloat162*)(ob + (size_t)(r0 + 8) * CH + co) =
                __floats2bfloat162_rn(o[mt][nv][2], o[mt][nv][3]);
        }
}

// ---------------------------------------------------------------------------
// launch
// ---------------------------------------------------------------------------
extern "C" void kernel_launch(void* const* d_in, const int* in_sizes, int n_in,
                              void* d_out, int out_size) {
    (void)in_sizes; (void)n_in; (void)out_size;
    const float* x     = (const float*)d_in[0];
    const float* n1g   = (const float*)d_in[3];
    const float* n1b   = (const float*)d_in[4];
    const float* qkvw  = (const float*)d_in[5];
    const float* qkvb  = (const float*)d_in[6];
    const float* projw = (const float*)d_in[7];
    const float* projb = (const float*)d_in[8];
    const float* rbt   = (const float*)d_in[9];
    const float* n2g   = (const float*)d_in[10];
    const float* n2b   = (const float*)d_in[11];
    const float* fc1w  = (const float*)d_in[12];
    const float* fc1b  = (const float*)d_in[13];
    const float* fc2w  = (const float*)d_in[14];
    const float* fc2b  = (const float*)d_in[15];
    float* out = (float*)d_out;

    bf16 *xw, *qkvb2, *attnb, *ln2, *h1, *wall;
    float *x1;
    cudaGetSymbolAddress((void**)&xw,    g_xw);
    cudaGetSymbolAddress((void**)&qkvb2, g_qkvb);
    cudaGetSymbolAddress((void**)&attnb, g_attn);
    cudaGetSymbolAddress((void**)&x1,    g_x1);
    cudaGetSymbolAddress((void**)&ln2,   g_ln2);
    cudaGetSymbolAddress((void**)&h1,    g_h1);
    cudaGetSymbolAddress((void**)&wall,  g_wall);

    cudaFuncSetAttribute(attn_mma, cudaFuncAttributeMaxDynamicSharedMemorySize, ATTN_SMEM);
    cudaFuncSetAttribute(hgemm_fc2, cudaFuncAttributeMaxDynamicSharedMemorySize, GSMEM);
    cudaFuncSetAttribute((agemm<3, 6>), cudaFuncAttributeMaxDynamicSharedMemorySize, ARSMEM);
    cudaFuncSetAttribute((agemm<4, 2>), cudaFuncAttributeMaxDynamicSharedMemorySize, ARSMEM);
    cudaFuncSetAttribute((agemm<1, 8>), cudaFuncAttributeMaxDynamicSharedMemorySize, ARSMEM);

    // 0. all weight conversions in one launch
    wconv_all<<<(W_TOTAL + 255) / 256, 256>>>(qkvw, projw, fc1w, fc2w, wall);

    // 1. LN1 + shift + partition
    ln1_kernel<<<TOT / 8, 256>>>(x, n1g, n1b, xw);

    // 2. qkv GEMM (A-resident) -> bf16, q pre-scaled
    agemm<3, 6><<<TOT / 128, 256, ARSMEM>>>(xw, wall + W_QKV_OFF, qkvb, nullptr, qkvb2);

    // 3. attention (tensor cores)
    attn_mma<<<NWIN, 384, ATTN_SMEM>>>(qkvb2, rbt, attnb);

    // 4. proj GEMM (A-resident) + window-reverse + roll + residual -> x1
    agemm<4, 2><<<TOT / 128, 256, ARSMEM>>>(attnb, wall + W_PROJ_OFF, projb, x, x1);

    // 5. LN2
    ln2_kernel<<<TOT / 8, 256>>>(x1, n2g, n2b, ln2);

    // 6. fc1 + gelu (A-resident) -> bf16
    agemm<1, 8><<<TOT / 128, 256, ARSMEM>>>(ln2, wall + W_FC1_OFF, fc1b, nullptr, h1);

    // 7. fc2 + residual -> out
    hgemm_fc2<<<dim3(2, TOT / 128), 256, GSMEM>>>(h1, wall + W_FC2_OFF, fc2b, x1, out);
}

// round 10
// speedup vs baseline: 1.0630x; 1.0630x over previous
#include <cuda_runtime.h>
#include <cuda_bf16.h>
#include <math.h>
#include <stdint.h>

// ---------------------------------------------------------------------------
// Problem constants
// ---------------------------------------------------------------------------
#define BATCH 8
#define HGT   128
#define WID   128
#define CH    192
#define NHEAD 6
#define HD    32
#define WS    8
#define SS    4
#define NTOK  64
#define NWIN  (BATCH * 16 * 16)       // 2048
#define TOT   (BATCH * HGT * WID)     // 131072
#define HID   (CH * 4)                // 768
#define QSCALE 0.17677669529663687f   // 32^-0.5

typedef __nv_bfloat16 bf16;

// ---------------------------------------------------------------------------
// Scratch (static device globals; allocation-free)
// ---------------------------------------------------------------------------
__device__ __align__(256) bf16  g_xw  [(size_t)TOT * CH];
__device__ __align__(256) bf16  g_qkvb[(size_t)TOT * 3 * CH];
__device__ __align__(256) bf16  g_attn[(size_t)TOT * CH];
__device__ __align__(256) float g_x1  [(size_t)TOT * CH];
__device__ __align__(256) bf16  g_ln2 [(size_t)TOT * CH];
__device__ __align__(256) bf16  g_h1  [(size_t)TOT * HID];
// one combined transposed-weight arena: [qkv | proj | fc1 | fc2]
#define W_QKV_OFF  0
#define W_PROJ_OFF (3 * CH * CH)
#define W_FC1_OFF  (W_PROJ_OFF + CH * CH)
#define W_FC2_OFF  (W_FC1_OFF + HID * CH)
#define W_TOTAL    (W_FC2_OFF + CH * HID)
__device__ __align__(256) bf16  g_wall[W_TOTAL];

// ---------------------------------------------------------------------------
// helpers
// ---------------------------------------------------------------------------
__device__ __forceinline__ uint32_t smem_u32(const void* p) {
    uint32_t a;
    asm("{ .reg .u64 t; cvta.to.shared.u64 t, %1; cvt.u32.u64 %0, t; }" : "=r"(a) : "l"(p));
    return a;
}
__device__ __forceinline__ void cpasync16(uint32_t so, const void* g) {
    asm volatile("cp.async.cg.shared.global [%0], [%1], 16;"
                 :: "r"(so), "l"(__cvta_generic_to_global(g)) : "memory");
}
__device__ __forceinline__ void ldm_x4(uint32_t* r, uint32_t addr) {
    asm volatile("ldmatrix.sync.aligned.m8n8.x4.shared.b16 {%0,%1,%2,%3}, [%4];"
                 : "=r"(r[0]), "=r"(r[1]), "=r"(r[2]), "=r"(r[3]) : "r"(addr));
}
__device__ __forceinline__ void ldm_x4t(uint32_t* r, uint32_t addr) {
    asm volatile("ldmatrix.sync.aligned.m8n8.x4.trans.shared.b16 {%0,%1,%2,%3}, [%4];"
                 : "=r"(r[0]), "=r"(r[1]), "=r"(r[2]), "=r"(r[3]) : "r"(addr));
}
__device__ __forceinline__ void mma16816(float* d, const uint32_t* a, const uint32_t* b) {
    asm volatile("mma.sync.aligned.m16n8k16.row.col.f32.bf16.bf16.f32 "
                 "{%0,%1,%2,%3}, {%4,%5,%6,%7}, {%8,%9}, {%0,%1,%2,%3};"
                 : "+f"(d[0]), "+f"(d[1]), "+f"(d[2]), "+f"(d[3])
                 : "r"(a[0]), "r"(a[1]), "r"(a[2]), "r"(a[3]), "r"(b[0]), "r"(b[1]));
}
__device__ __forceinline__ uint32_t packbf(float a, float b) {
    __nv_bfloat162 t = __floats2bfloat162_rn(a, b);
    return *(uint32_t*)&t;
}

// ---------------------------------------------------------------------------
// Combined weight transpose+convert (one launch).  Wt[n*K+k] = bf16(W[k*N+n])
// ---------------------------------------------------------------------------
__global__ void wconv_all(const float* __restrict__ Wqkv, const float* __restrict__ Wproj,
                          const float* __restrict__ Wfc1, const float* __restrict__ Wfc2,
                          bf16* __restrict__ arena) {
    int i = blockIdx.x * 256 + threadIdx.x;
    const float* W; int K, N, off;
    if (i < W_PROJ_OFF)            { W = Wqkv;  K = CH;  N = 3 * CH; off = 0;          }
    else if (i < W_FC1_OFF)        { W = Wproj; K = CH;  N = CH;     off = W_PROJ_OFF; }
    else if (i < W_FC2_OFF)        { W = Wfc1;  K = CH;  N = HID;    off = W_FC1_OFF;  }
    else if (i < W_TOTAL)          { W = Wfc2;  K = HID; N = CH;     off = W_FC2_OFF;  }
    else return;
    int j = i - off;
    int n = j / K, k = j - n * K;
    arena[i] = __float2bfloat16(W[(size_t)k * N + n]);
}

// ---------------------------------------------------------------------------
// K1: LN1 + roll(-4,-4) + window partition -> bf16.  Warp per row.
// ---------------------------------------------------------------------------
__global__ void __launch_bounds__(256) ln1_kernel(const float* __restrict__ x,
                                                  const float* __restrict__ g,
                                                  const float* __restrict__ b,
                                                  bf16* __restrict__ out) {
    int row  = blockIdx.x * 8 + (threadIdx.x >> 5);
    int lane = threadIdx.x & 31;
    int win = row >> 6, n = row & 63;
    int bimg = win >> 8;
    int wii  = win & 255;
    int sy = ((wii >> 4) * 8 + (n >> 3) + SS) & 127;
    int sx = ((wii & 15) * 8 + (n & 7) + SS) & 127;
    const float* xr = x + ((size_t)bimg * (HGT * WID) + sy * WID + sx) * CH;

    float v[6];
    #pragma unroll
    for (int i = 0; i < 6; i++) v[i] = xr[lane + 32 * i];
    float s = v[0] + v[1] + v[2] + v[3] + v[4] + v[5];
    #pragma unroll
    for (int o = 16; o > 0; o >>= 1) s += __shfl_xor_sync(~0u, s, o);
    float mu = s * (1.0f / CH);
    float q = 0.f;
    #pragma unroll
    for (int i = 0; i < 6; i++) { v[i] -= mu; q += v[i] * v[i]; }
    #pragma unroll
    for (int o = 16; o > 0; o >>= 1) q += __shfl_xor_sync(~0u, q, o);
    float rs = rsqrtf(q * (1.0f / CH) + 1e-5f);
    bf16* orow = out + (size_t)row * CH;
    #pragma unroll
    for (int i = 0; i < 6; i++) {
        int c = lane + 32 * i;
        orow[c] = __float2bfloat16(v[i] * rs * g[c] + b[c]);
    }
}

// ---------------------------------------------------------------------------
// LN2 only (token order).  Warp per row.
// ---------------------------------------------------------------------------
__global__ void __launch_bounds__(256) ln2_kernel(const float* __restrict__ x1,
                                                  const float* __restrict__ g,
                                                  const float* __restrict__ b,
                                                  bf16* __restrict__ out) {
    int row  = blockIdx.x * 8 + (threadIdx.x >> 5);
    int lane = threadIdx.x & 31;
    const float* xr = x1 + (size_t)row * CH;
    float v[6];
    #pragma unroll
    for (int i = 0; i < 6; i++) v[i] = xr[lane + 32 * i];
    float s = v[0] + v[1] + v[2] + v[3] + v[4] + v[5];
    #pragma unroll
    for (int o = 16; o > 0; o >>= 1) s += __shfl_xor_sync(~0u, s, o);
    float mu = s * (1.0f / CH);
    float q = 0.f;
    #pragma unroll
    for (int i = 0; i < 6; i++) { v[i] -= mu; q += v[i] * v[i]; }
    #pragma unroll
    for (int o = 16; o > 0; o >>= 1) q += __shfl_xor_sync(~0u, q, o);
    float rs = rsqrtf(q * (1.0f / CH) + 1e-5f);
    bf16* orow = out + (size_t)row * CH;
    #pragma unroll
    for (int i = 0; i < 6; i++) {
        int c = lane + 32 * i;
        orow[c] = __float2bfloat16(v[i] * rs * g[c] + b[c]);
    }
}

// ---------------------------------------------------------------------------
// HMMA GEMM: BM=128 BN=96 BK=32, 256 thr (8 warps, warp tile 32x48),
// 3-stage cp.async ring, one barrier per chunk, 2 CTAs/SM.  (round-6 config)
// EPI 1: gelu->bf16   2: +res->fp32   3: qkv bf16 (scale q cols)   4: proj permute+res->x1
// ---------------------------------------------------------------------------
#define PITCH 80
#define A_STG (128 * PITCH)          // 10240
#define B_STG (96 * PITCH)           // 7680
#define STG   (A_STG + B_STG)        // 17920
#define GSMEM (3 * STG)              // 53760

__device__ __forceinline__ void load_stage(uint32_t st, const bf16* Ag, const bf16* Bg,
                                           int Kbig, int tid) {
    #pragma unroll
    for (int i = 0; i < 2; i++) {
        int t = tid + i * 256;
        int row = t >> 2, seg = t & 3;
        cpasync16(st + row * PITCH + seg * 16, Ag + (size_t)row * Kbig + seg * 8);
    }
    #pragma unroll
    for (int i = 0; i < 2; i++) {
        int t = tid + i * 256;
        if (t < 384) {
            int row = t >> 2, seg = t & 3;
            cpasync16(st + A_STG + row * PITCH + seg * 16, Bg + (size_t)row * Kbig + seg * 8);
        }
    }
}

// window-layout row -> token index (reverse partition + roll(+4,+4))
__device__ __forceinline__ int row2tok(int row) {
    int win = row >> 6, n = row & 63;
    int bimg = win >> 8;
    int wii  = win & 255;
    int y = ((wii >> 4) * 8 + (n >> 3) + SS) & 127;
    int x = ((wii & 15) * 8 + (n & 7) + SS) & 127;
    return bimg * (HGT * WID) + y * WID + x;
}

template <int EPI>
__global__ void __launch_bounds__(256) hgemm(const bf16* __restrict__ A,
                                             const bf16* __restrict__ Bt,
                                             const float* __restrict__ bias,
                                             const float* __restrict__ res,
                                             void* __restrict__ Cout,
                                             int Kbig, int Nbig) {
    extern __shared__ __align__(128) char smem[];
    __shared__ float sbias[96];

    const int tid  = threadIdx.x;
    const int lane = tid & 31;
    const int w    = tid >> 5;
    const int bm   = blockIdx.y * 128;
    const int bn   = blockIdx.x * 96;
    const int wm   = (w & 3) * 32;
    const int wn   = (w >> 2) * 48;

    const uint32_t sb = smem_u32(smem);
    if (tid < 96) sbias[tid] = bias[bn + tid];

    const bf16* Ag = A  + (size_t)bm * Kbig;
    const bf16* Bg = Bt + (size_t)bn * Kbig;
    const int NC = Kbig >> 5;

    const int aRow = (lane & 7) + ((lane >> 3) & 1) * 8;
    const int aCol = (lane >> 4) * 8;
    const int bRow = (lane & 7) + (lane >> 4) * 8;
    const int bCol = ((lane >> 3) & 1) * 8;

    float acc[2][6][4];
    #pragma unroll
    for (int i = 0; i < 2; i++)
        #pragma unroll
        for (int j = 0; j < 6; j++)
            #pragma unroll
            for (int k = 0; k < 4; k++) acc[i][j][k] = 0.0f;

    load_stage(sb, Ag, Bg, Kbig, tid);
    asm volatile("cp.async.commit_group;" ::: "memory");
    if (NC > 1) {
        load_stage(sb + STG, Ag + 32, Bg + 32, Kbig, tid);
        asm volatile("cp.async.commit_group;" ::: "memory");
    }

    for (int c = 0; c < NC; c++) {
        if (c + 1 < NC) asm volatile("cp.async.wait_group 1;" ::: "memory");
        else            asm volatile("cp.async.wait_group 0;" ::: "memory");
        __syncthreads();

        if (c + 2 < NC) {
            load_stage(sb + ((c + 2) % 3) * STG,
                       Ag + (size_t)(c + 2) * 32, Bg + (size_t)(c + 2) * 32, Kbig, tid);
            asm volatile("cp.async.commit_group;" ::: "memory");
        }

        const uint32_t cA = sb + (c % 3) * STG;
        const uint32_t cB = cA + A_STG;

        #pragma unroll
        for (int ks = 0; ks < 2; ks++) {
            uint32_t af[2][4], bf_[3][4];
            #pragma unroll
            for (int mt = 0; mt < 2; mt++)
                ldm_x4(af[mt], cA + (wm + mt * 16 + aRow) * PITCH + (ks * 16 + aCol) * 2);
            #pragma unroll
            for (int nt = 0; nt < 3; nt++)
                ldm_x4(bf_[nt], cB + (wn + nt * 16 + bRow) * PITCH + (ks * 16 + bCol) * 2);
            #pragma unroll
            for (int mt = 0; mt < 2; mt++)
                #pragma unroll
                for (int nt = 0; nt < 3; nt++) {
                    mma16816(acc[mt][2 * nt + 0], af[mt], bf_[nt] + 0);
                    mma16816(acc[mt][2 * nt + 1], af[mt], bf_[nt] + 2);
                }
        }
    }

    const int g = lane >> 2, t4 = lane & 3;
    #pragma unroll
    for (int mi = 0; mi < 2; mi++) {
        #pragma unroll
        for (int ni = 0; ni < 6; ni++) {
            int colL = wn + ni * 8 + t4 * 2;
            int col  = bn + colL;
            int row0 = bm + wm + mi * 16 + g;
            int row1 = row0 + 8;
            float v00 = acc[mi][ni][0] + sbias[colL];
            float v01 = acc[mi][ni][1] + sbias[colL + 1];
            float v10 = acc[mi][ni][2] + sbias[colL];
            float v11 = acc[mi][ni][3] + sbias[colL + 1];
            if (EPI == 1) {
                v00 = v00 * normcdff(v00); v01 = v01 * normcdff(v01);
                v10 = v10 * normcdff(v10); v11 = v11 * normcdff(v11);
                bf16* C = (bf16*)Cout;
                *(__nv_bfloat162*)(C + (size_t)row0 * Nbig + col) = __floats2bfloat162_rn(v00, v01);
                *(__nv_bfloat162*)(C + (size_t)row1 * Nbig + col) = __floats2bfloat162_rn(v10, v11);
            } else if (EPI == 2) {
                float2 r0 = *(const float2*)(res + (size_t)row0 * Nbig + col);
                float2 r1 = *(const float2*)(res + (size_t)row1 * Nbig + col);
                float* C = (float*)Cout;
                *(float2*)(C + (size_t)row0 * Nbig + col) = make_float2(v00 + r0.x, v01 + r0.y);
                *(float2*)(C + (size_t)row1 * Nbig + col) = make_float2(v10 + r1.x, v11 + r1.y);
            } else if (EPI == 3) {
                float s = (col < CH) ? QSCALE : 1.0f;
                bf16* C = (bf16*)Cout;
                *(__nv_bfloat162*)(C + (size_t)row0 * Nbig + col) = __floats2bfloat162_rn(v00 * s, v01 * s);
                *(__nv_bfloat162*)(C + (size_t)row1 * Nbig + col) = __floats2bfloat162_rn(v10 * s, v11 * s);
            } else { // EPI 4
                int t0 = row2tok(row0), t1 = row2tok(row1);
                float2 r0 = *(const float2*)(res + (size_t)t0 * Nbig + col);
                float2 r1 = *(const float2*)(res + (size_t)t1 * Nbig + col);
                float* C = (float*)Cout;
                *(float2*)(C + (size_t)t0 * Nbig + col) = make_float2(v00 + r0.x, v01 + r0.y);
                *(float2*)(C + (size_t)t1 * Nbig + col) = make_float2(v10 + r1.x, v11 + r1.y);
            }
        }
    }
}

// ---------------------------------------------------------------------------
// K3: attention with mma.sync.  One CTA per window, 384 thr = 2 warps/head.
// Row-halves (mt) processed SEQUENTIALLY to cut live registers -> 2 CTAs/SM.
// ---------------------------------------------------------------------------
#define APB 400
#define ATTN_SMEM (3 * 64 * APB + 6 * 225 * 4 + 64 * 4)

__global__ void __launch_bounds__(384, 2) attn_mma(const bf16* __restrict__ qkv,
                                                   const float* __restrict__ bt,
                                                   bf16* __restrict__ out) {
    extern __shared__ __align__(128) char sm[];
    const uint32_t sb = smem_u32(sm);
    const uint32_t sQ = sb, sK = sb + 64 * APB, sV = sb + 128 * APB;
    float* sbias = (float*)(sm + 3 * 64 * APB);
    int*   sreg  = (int*)(sm + 3 * 64 * APB + 6 * 225 * 4);

    const int tid  = threadIdx.x;
    const int win  = blockIdx.x;
    const int lane = tid & 31;
    const int wid  = tid >> 5;
    const int head = wid >> 1, half = wid & 1;
    const int g = lane >> 2, t4 = lane & 3;

    const bf16* gbase = qkv + (size_t)win * NTOK * (3 * CH);
    #pragma unroll
    for (int i = 0; i < 12; i++) {
        int c = tid + i * 384;
        int r = c / 72, w2 = c % 72;
        int tile = w2 / 24, seg = w2 % 24;
        cpasync16(sb + tile * (64 * APB) + r * APB + seg * 16,
                  gbase + (size_t)r * (3 * CH) + tile * CH + seg * 8);
    }
    asm volatile("cp.async.commit_group;" ::: "memory");

    for (int i = tid; i < 6 * 225; i += 384) {
        int h = i / 225, p = i - h * 225;
        sbias[i] = bt[p * NHEAD + h];
    }
    if (tid < 64) {
        int wii = win & 255;
        int y = (wii >> 4) * 8 + (tid >> 3);
        int x = (wii & 15) * 8 + (tid & 7);
        int ry = (y < 120) ? 0 : (y < 124 ? 1 : 2);
        int rx = (x < 120) ? 0 : (x < 124 ? 1 : 2);
        sreg[tid] = ry * 3 + rx;
    }
    asm volatile("cp.async.wait_group 0;" ::: "memory");
    __syncthreads();

    const int aRow = (lane & 7) + ((lane >> 3) & 1) * 8;
    const int aCol = (lane >> 4) * 8;
    const int bRow = (lane & 7) + (lane >> 4) * 8;
    const int bCol = ((lane >> 3) & 1) * 8;
    const float* bh = sbias + head * 225;
    bf16* ob = out + (size_t)win * NTOK * CH + head * HD;

    #pragma unroll 1
    for (int mt = 0; mt < 2; mt++) {
        const int rbase = half * 32 + mt * 16;

        // Q fragments for this 16-row block
        uint32_t qf[2][4];
        #pragma unroll
        for (int ks = 0; ks < 2; ks++)
            ldm_x4(qf[ks], sQ + (rbase + aRow) * APB + (head * 32 + ks * 16 + aCol) * 2);

        // scores = Q K^T   (16 x 64)
        float sc[8][4];
        #pragma unroll
        for (int b2 = 0; b2 < 8; b2++)
            #pragma unroll
            for (int c2 = 0; c2 < 4; c2++) sc[b2][c2] = 0.f;

        #pragma unroll
        for (int nt = 0; nt < 4; nt++) {
            uint32_t kb[2][4];
            #pragma unroll
            for (int ks = 0; ks < 2; ks++)
                ldm_x4(kb[ks], sK + (nt * 16 + bRow) * APB + (head * 32 + ks * 16 + bCol) * 2);
            #pragma unroll
            for (int ks = 0; ks < 2; ks++) {
                mma16816(sc[2 * nt + 0], qf[ks], kb[ks] + 0);
                mma16816(sc[2 * nt + 1], qf[ks], kb[ks] + 2);
            }
        }

        // bias + mask + softmax
        float inv[2];
        #pragma unroll
        for (int s = 0; s < 2; s++) {
            int row = rbase + g + 8 * s;
            int ty = row >> 3, tx = row & 7;
            int myreg = sreg[row];
            float mx = -1e30f;
            #pragma unroll
            for (int nt = 0; nt < 8; nt++)
                #pragma unroll
                for (int i = 0; i < 2; i++) {
                    int col = nt * 8 + t4 * 2 + i;
                    float v = sc[nt][2 * s + i]
                            + bh[(ty - (col >> 3) + 7) * 15 + (tx - (col & 7) + 7)];
                    if (sreg[col] != myreg) v -= 100.f;
                    sc[nt][2 * s + i] = v;
                    mx = fmaxf(mx, v);
                }
            mx = fmaxf(mx, __shfl_xor_sync(~0u, mx, 1));
            mx = fmaxf(mx, __shfl_xor_sync(~0u, mx, 2));
            float sum = 0.f;
            #pragma unroll
            for (int nt = 0; nt < 8; nt++)
                #pragma unroll
                for (int i = 0; i < 2; i++) {
                    float e = __expf(sc[nt][2 * s + i] - mx);
                    sc[nt][2 * s + i] = e;
                    sum += e;
                }
            sum += __shfl_xor_sync(~0u, sum, 1);
            sum += __shfl_xor_sync(~0u, sum, 2);
            inv[s] = 1.0f / sum;
        }

        // pack normalized P into A fragments
        uint32_t pf[4][4];
        #pragma unroll
        for (int kt = 0; kt < 4; kt++) {
            pf[kt][0] = packbf(sc[2 * kt][0] * inv[0], sc[2 * kt][1] * inv[0]);
            pf[kt][1] = packbf(sc[2 * kt][2] * inv[1], sc[2 * kt][3] * inv[1]);
            pf[kt][2] = packbf(sc[2 * kt + 1][0] * inv[0], sc[2 * kt + 1][1] * inv[0]);
            pf[kt][3] = packbf(sc[2 * kt + 1][2] * inv[1], sc[2 * kt + 1][3] * inv[1]);
        }

        // O = P V
        float o[4][4];
        #pragma unroll
        for (int b2 = 0; b2 < 4; b2++)
            #pragma unroll
            for (int c2 = 0; c2 < 4; c2++) o[b2][c2] = 0.f;

        #pragma unroll
        for (int kt = 0; kt < 4; kt++)
            #pragma unroll
            for (int nv = 0; nv < 2; nv++) {
                uint32_t vb[4];
                ldm_x4t(vb, sV + (kt * 16 + (lane & 7) + ((lane >> 3) & 1) * 8) * APB
                           + (head * 32 + nv * 16 + (lane >> 4) * 8) * 2);
                mma16816(o[2 * nv + 0], pf[kt], vb + 0);
                mma16816(o[2 * nv + 1], pf[kt], vb + 2);
            }

        // store
        #pragma unroll
        for (int nv = 0; nv < 4; nv++) {
            int r0 = rbase + g;
            int co = nv * 8 + t4 * 2;
            *(__nv_bfloat162*)(ob + (size_t)r0 * CH + co) =
                __floats2bfloat162_rn(o[nv][0], o[nv][1]);
            *(__nv_bfloat162*)(ob + (size_t)(r0 + 8) * CH + co) =
                __floats2bfloat162_rn(o[nv][2], o[nv][3]);
        }
    }
}

// ---------------------------------------------------------------------------
// launch
// ---------------------------------------------------------------------------
extern "C" void kernel_launch(void* const* d_in, const int* in_sizes, int n_in,
                              void* d_out, int out_size) {
    (void)in_sizes; (void)n_in; (void)out_size;
    const float* x     = (const float*)d_in[0];
    const float* n1g   = (const float*)d_in[3];
    const float* n1b   = (const float*)d_in[4];
    const float* qkvw  = (const float*)d_in[5];
    const float* qkvb  = (const float*)d_in[6];
    const float* projw = (const float*)d_in[7];
    const float* projb = (const float*)d_in[8];
    const float* rbt   = (const float*)d_in[9];
    const float* n2g   = (const float*)d_in[10];
    const float* n2b   = (const float*)d_in[11];
    const float* fc1w  = (const float*)d_in[12];
    const float* fc1b  = (const float*)d_in[13];
    const float* fc2w  = (const float*)d_in[14];
    const float* fc2b  = (const float*)d_in[15];
    float* out = (float*)d_out;

    bf16 *xw, *qkvb2, *attnb, *ln2, *h1, *wall;
    float *x1;
    cudaGetSymbolAddress((void**)&xw,    g_xw);
    cudaGetSymbolAddress((void**)&qkvb2, g_qkvb);
    cudaGetSymbolAddress((void**)&attnb, g_attn);
    cudaGetSymbolAddress((void**)&x1,    g_x1);
    cudaGetSymbolAddress((void**)&ln2,   g_ln2);
    cudaGetSymbolAddress((void**)&h1,    g_h1);
    cudaGetSymbolAddress((void**)&wall,  g_wall);

    cudaFuncSetAttribute(attn_mma, cudaFuncAttributeMaxDynamicSharedMemorySize, ATTN_SMEM);
    cudaFuncSetAttribute(hgemm<1>, cudaFuncAttributeMaxDynamicSharedMemorySize, GSMEM);
    cudaFuncSetAttribute(hgemm<2>, cudaFuncAttributeMaxDynamicSharedMemorySize, GSMEM);
    cudaFuncSetAttribute(hgemm<3>, cudaFuncAttributeMaxDynamicSharedMemorySize, GSMEM);
    cudaFuncSetAttribute(hgemm<4>, cudaFuncAttributeMaxDynamicSharedMemorySize, GSMEM);

    // 0. all weight conversions in one launch
    wconv_all<<<(W_TOTAL + 255) / 256, 256>>>(qkvw, projw, fc1w, fc2w, wall);

    // 1. LN1 + shift + partition
    ln1_kernel<<<TOT / 8, 256>>>(x, n1g, n1b, xw);

    // 2. qkv GEMM -> bf16, q pre-scaled   (576 = 6 x 96)
    hgemm<3><<<dim3(6, TOT / 128), 256, GSMEM>>>(xw, wall + W_QKV_OFF, qkvb, nullptr,
                                                 qkvb2, CH, 3 * CH);

    // 3. attention (tensor cores, low-register)
    attn_mma<<<NWIN, 384, ATTN_SMEM>>>(qkvb2, rbt, attnb);

    // 4. proj GEMM + window-reverse + roll + residual -> x1 (token order)  (192 = 2 x 96)
    hgemm<4><<<dim3(2, TOT / 128), 256, GSMEM>>>(attnb, wall + W_PROJ_OFF, projb, x,
                                                 x1, CH, CH);

    // 5. LN2
    ln2_kernel<<<TOT / 8, 256>>>(x1, n2g, n2b, ln2);

    // 6. fc1 + gelu -> bf16   (768 = 8 x 96)
    hgemm<1><<<dim3(8, TOT / 128), 256, GSMEM>>>(ln2, wall + W_FC1_OFF, fc1b, nullptr,
                                                 h1, CH, HID);

    // 7. fc2 + residual -> out   (192 = 2 x 96)
    hgemm<2><<<dim3(2, TOT / 128), 256, GSMEM>>>(h1, wall + W_FC2_OFF, fc2b, x1,
                                                 out, HID, CH);
}